// round 1
// baseline (speedup 1.0000x reference)
#include <cuda_runtime.h>

#define HH 512
#define WW 512
#define TX 32
#define TY 32
#define GHALO 3                 // gates / owned-pixel halo
#define RHALO 4                 // initial result halo
#define GS (TX + 2 * GHALO)     // 38
#define RS (TX + 2 * RHALO)     // 40
#define NPX (GS * GS)           // 1444 owned pixels per tile
#define NTH 512                 // threads per CTA
#define QMAX 3                  // owned pixels per thread (512*3 >= 1444)
#define NACT2 (NPX - 2 * NTH)   // 420: q=2 active threshold

__global__ __launch_bounds__(NTH, 2)
void affinity_prop_kernel(const float* __restrict__ guid,
                          const float* __restrict__ blur,
                          float* __restrict__ out)
{
    __shared__ float res[2][RS * RS];

    const int tid = threadIdx.x;
    const int b   = blockIdx.z;
    const int oy  = blockIdx.y * TY;
    const int ox  = blockIdx.x * TX;

    const float* __restrict__ blurb = blur + (size_t)b * HH * WW;
    const float* __restrict__ guidb = guid + (size_t)b * 8 * HH * WW;

    // Neighbor offsets: shifted[i,j] = x[i+di, j+dj]
    const int di[8] = { 1, 1, 1, 0, 0, -1, -1, -1 };
    const int dj[8] = { 1, 0,-1, 1,-1,  1,  0, -1 };

    // ---- Load initial result (blur_depth) with halo RHALO into BOTH buffers ----
    #pragma unroll
    for (int i = tid; i < RS * RS; i += NTH) {
        int ly = i / RS, lx = i % RS;
        int y = oy - RHALO + ly;
        int x = ox - RHALO + lx;
        float v = 0.0f;
        if ((unsigned)y < HH && (unsigned)x < WW)
            v = __ldg(&blurb[y * WW + x]);
        res[0][i] = v;
        res[1][i] = v;
    }
    __syncthreads();

    // ---- Per-thread owned pixels: compute normalized gates into registers ----
    float g[QMAX][8];
    float omgs[QMAX];   // 1 - gate_sum
    float rawv[QMAX];   // original blur value at owned pixel
    int   rbase[QMAX];  // smem index of owned pixel in res buffer
    int   oidx[QMAX];   // gmem output index
    bool  wout[QMAX];   // true if owned pixel is in the inner 32x32 output tile

    #pragma unroll
    for (int q = 0; q < QMAX; q++) {
        int p = q * NTH + tid;
        bool act = (p < NPX);
        int pp = act ? p : 0;
        int gy = pp / GS, gx = pp % GS;
        int y = oy - GHALO + gy;
        int x = ox - GHALO + gx;
        bool in = act && ((unsigned)y < HH) && ((unsigned)x < WW);

        rbase[q] = (gy + (RHALO - GHALO)) * RS + (gx + (RHALO - GHALO));

        float a = 0.0f;
        #pragma unroll
        for (int k = 0; k < 8; k++) {
            int yy = y + di[k];
            int xx = x + dj[k];
            float v = 0.0f;
            if (in && (unsigned)yy < HH && (unsigned)xx < WW)
                v = __ldg(&guidb[(k * HH + yy) * WW + xx]);
            g[q][k] = v;
            a += fabsf(v);
        }
        float inva = in ? (1.0f / a) : 0.0f;   // in-image pixels always have a > 0
        float gs = 0.0f;
        #pragma unroll
        for (int k = 0; k < 8; k++) {
            g[q][k] *= inva;
            gs += g[q][k];
        }
        omgs[q] = in ? (1.0f - gs) : 0.0f;
        rawv[q] = res[0][rbase[q]];            // blur at own pixel (0 if OOB)

        wout[q] = in && gy >= GHALO && gy < GHALO + TY
                     && gx >= GHALO && gx < GHALO + TX;
        oidx[q] = y * WW + x;
    }

    // ---- 4 fused propagation iterations ----
    int cur = 0;
    #pragma unroll
    for (int t = 0; t < 4; t++) {
        float val[QMAX];
        const float* __restrict__ rc = res[cur];
        #pragma unroll
        for (int q = 0; q < QMAX; q++) {
            float s = omgs[q] * rawv[q];
            int rb = rbase[q];
            #pragma unroll
            for (int k = 0; k < 8; k++)
                s += g[q][k] * rc[rb + di[k] * RS + dj[k]];
            val[q] = s;
        }

        if (t < 3) {
            float* __restrict__ rn = res[cur ^ 1];
            rn[rbase[0]] = val[0];
            rn[rbase[1]] = val[1];
            if (tid < NACT2) rn[rbase[2]] = val[2];
            __syncthreads();
            cur ^= 1;
        } else {
            float* __restrict__ outb = out + (size_t)b * HH * WW;
            #pragma unroll
            for (int q = 0; q < QMAX; q++)
                if (wout[q]) outb[oidx[q]] = val[q];
        }
    }
}

extern "C" void kernel_launch(void* const* d_in, const int* in_sizes, int n_in,
                              void* d_out, int out_size)
{
    // metadata order: guidance [B,8,H,W], blur_depth [B,1,H,W]
    const float* guid = (const float*)d_in[0];
    const float* blur = (const float*)d_in[1];
    int gsz = in_sizes[0];
    int bsz = in_sizes[1];
    if (n_in >= 2 && gsz < bsz) {   // defensive: handle swapped order
        const float* tmp = guid; guid = blur; blur = tmp;
        int t = gsz; gsz = bsz; bsz = t;
    }
    int batch = bsz / (HH * WW);

    dim3 grid(WW / TX, HH / TY, batch);
    affinity_prop_kernel<<<grid, NTH>>>(guid, blur, (float*)d_out);
}

// round 2
// speedup vs baseline: 1.0500x; 1.0500x over previous
#include <cuda_runtime.h>

#define HH 512
#define WW 512
#define TX 32
#define TY 32
#define GXS 38                    // gate region width  (gate x: global ox-3 .. ox+34)
#define GYS 40                    // gate region height, padded to /4 (gate y: oy-3 .. oy+36)
#define NSTRIP (GXS * (GYS / 4))  // 380 vertical 4-strips
#define NTH 384
#define RXS 40                    // res buffer width  (global x: ox-4 .. ox+35)
#define RYS 42                    // res buffer height (global y: oy-4 .. oy+37)

__global__ __launch_bounds__(NTH, 2)
void affinity_prop_kernel(const float* __restrict__ guid,
                          const float* __restrict__ blur,
                          float* __restrict__ out)
{
    __shared__ float res[2][RYS * RXS];

    const int tid = threadIdx.x;
    const int b   = blockIdx.z;
    const int oy  = blockIdx.y * TY;
    const int ox  = blockIdx.x * TX;

    const float* __restrict__ blurb = blur + (size_t)b * HH * WW;
    const float* __restrict__ guidb = guid + (size_t)b * 8 * HH * WW;

    // ---- Init both result buffers with blur_depth (zero-padded), halo 4 ----
    // res cell (ry, rx) <-> global (oy + ry - 4, ox + rx - 4)
    #pragma unroll
    for (int i = tid; i < RYS * RXS; i += NTH) {
        int ry = i / RXS, rx0 = i % RXS;
        int gy = oy + ry - 4, gx = ox + rx0 - 4;
        float v = 0.0f;
        if ((unsigned)gy < HH && (unsigned)gx < WW)
            v = __ldg(&blurb[gy * WW + gx]);
        res[0][i] = v;
        res[1][i] = v;
    }
    __syncthreads();

    // ---- Each thread owns a vertical strip of 4 pixels ----
    const bool active = tid < NSTRIP;
    const int  s   = active ? tid : 0;
    const int  sy  = s / GXS;            // strip row 0..9
    const int  sx  = s % GXS;            // gate x 0..37
    const int  x   = ox - 3 + sx;        // global x
    const int  y0  = oy - 3 + sy * 4;    // global y of strip top
    const int  rx  = sx + 1;             // res x index
    const int  ryb = sy * 4 + 1;         // res y index of strip top

    // shifted[i,j] = src[i+di, j+dj]
    const int di[8] = { 1, 1, 1, 0, 0, -1, -1, -1 };
    const int dj[8] = { 1, 0,-1, 1,-1,  1,  0, -1 };

    float g[4][8];   // normalized gates, per owned pixel
    float bias[4];   // (1 - gate_sum) * raw, constant across iterations
    float val[4];    // current result values of owned pixels (registers!)

    #pragma unroll
    for (int r = 0; r < 4; r++) {
        int y = y0 + r;
        bool in = active && ((unsigned)y < HH) && ((unsigned)x < WW);
        float a = 0.0f;
        #pragma unroll
        for (int k = 0; k < 8; k++) {
            int yy = y + di[k];
            int xx = x + dj[k];
            float v = 0.0f;
            if (in && (unsigned)yy < HH && (unsigned)xx < WW)
                v = __ldg(&guidb[(k * HH + yy) * WW + xx]);
            g[r][k] = v;
            a += fabsf(v);
        }
        float inva = in ? (1.0f / a) : 0.0f;
        float gs = 0.0f;
        #pragma unroll
        for (int k = 0; k < 8; k++) { g[r][k] *= inva; gs += g[r][k]; }
        float raw = res[0][(ryb + r) * RXS + rx];
        bias[r] = in ? (1.0f - gs) * raw : 0.0f;
        val[r]  = raw;
    }

    // ---- 4 fused propagation iterations ----
    #pragma unroll
    for (int t = 0; t < 4; t++) {
        const float* __restrict__ rc = res[t & 1];

        // Neighbor columns (lane-stride-1 -> conflict-free, 14 LDS per thread)
        float L[6], R[6], C[6];
        #pragma unroll
        for (int i = 0; i < 6; i++) {
            L[i] = rc[(ryb - 1 + i) * RXS + rx - 1];
            R[i] = rc[(ryb - 1 + i) * RXS + rx + 1];
        }
        C[0] = rc[(ryb - 1) * RXS + rx];
        C[1] = val[0]; C[2] = val[1]; C[3] = val[2]; C[4] = val[3];
        C[5] = rc[(ryb + 4) * RXS + rx];

        float nv[4];
        #pragma unroll
        for (int r = 0; r < 4; r++) {
            float sacc = bias[r];
            sacc += g[r][0] * R[r + 2];   // ( 1, 1)
            sacc += g[r][1] * C[r + 2];   // ( 1, 0)
            sacc += g[r][2] * L[r + 2];   // ( 1,-1)
            sacc += g[r][3] * R[r + 1];   // ( 0, 1)
            sacc += g[r][4] * L[r + 1];   // ( 0,-1)
            sacc += g[r][5] * R[r];       // (-1, 1)
            sacc += g[r][6] * C[r];       // (-1, 0)
            sacc += g[r][7] * L[r];       // (-1,-1)
            nv[r] = sacc;
        }
        #pragma unroll
        for (int r = 0; r < 4; r++) val[r] = nv[r];

        if (t < 3) {
            float* __restrict__ rn = res[(t & 1) ^ 1];
            if (active) {
                #pragma unroll
                for (int r = 0; r < 4; r++)
                    rn[(ryb + r) * RXS + rx] = val[r];
            }
            __syncthreads();
        }
    }

    // ---- Write inner 32x32 ----
    float* __restrict__ outb = out + (size_t)b * HH * WW;
    #pragma unroll
    for (int r = 0; r < 4; r++) {
        int gy = sy * 4 + r;
        if (active && gy >= 3 && gy < 3 + TY && sx >= 3 && sx < 3 + TX)
            outb[(y0 + r) * WW + x] = val[r];
    }
}

extern "C" void kernel_launch(void* const* d_in, const int* in_sizes, int n_in,
                              void* d_out, int out_size)
{
    const float* guid = (const float*)d_in[0];
    const float* blur = (const float*)d_in[1];
    int gsz = in_sizes[0];
    int bsz = in_sizes[1];
    if (n_in >= 2 && gsz < bsz) {   // defensive: handle swapped order
        const float* tmp = guid; guid = blur; blur = tmp;
        int t = gsz; gsz = bsz; bsz = t;
    }
    int batch = bsz / (HH * WW);

    dim3 grid(WW / TX, HH / TY, batch);
    affinity_prop_kernel<<<grid, NTH>>>(guid, blur, (float*)d_out);
}